// round 7
// baseline (speedup 1.0000x reference)
#include <cuda_runtime.h>

#define NCHUNKS 32
#define WARPS   32
#define ROWS    64
#define THREADS 1024
#define MAX_ATOMS   16384
#define MAX_CLAUSES 4096

// Packed per-atom metadata: {A', B', (fid*256)|lastFlag(bit31), gate*leaf[cid] if last}
// arg = A'*x[fid] + B' ;  e = exp2(arg) = exp(-z) ;  sigmoid(z) = 1/(1+e)
// clause value = 1 / prod(1+e) ; accumulated when lastFlag set.
// fid is pre-scaled to a byte offset into the feature-major smem tile
// (stride ROWS*4 = 256 bytes per feature).
__device__ float4 g_meta[MAX_ATOMS];
__device__ int    g_chunk_start[NCHUNKS + 1]; // clause-aligned atom ranges
__device__ float  g_empty[NCHUNKS];           // sum of g over EMPTY clauses per chunk

__device__ __forceinline__ float ex2a(float a) {
    float r; asm("ex2.approx.f32 %0, %1;" : "=f"(r) : "f"(a)); return r;
}
__device__ __forceinline__ float rcpa(float a) {
    float r; asm("rcp.approx.f32 %0, %1;" : "=f"(r) : "f"(a)); return r;
}

__global__ void cln_setup(const float* __restrict__ w,
                          const float* __restrict__ eta,
                          const float* __restrict__ leaf,
                          const float* __restrict__ gate,
                          const int* __restrict__ fid,
                          const int* __restrict__ csgn,
                          const int* __restrict__ cids,
                          int n_atoms, int n_clauses, int cpc) {
    int i = blockIdx.x * blockDim.x + threadIdx.x;
    const float L2E = 1.4426950408889634f;   // log2(e)
    if (i < n_atoms) {
        float sB = (csgn[i] == 0) ? -100.0f : 100.0f;   // sign * B_CONST
        float A2 = -sB * w[i] * L2E;
        float B2 = -sB * (0.01f - eta[i]) * L2E;        // EPS = 0.01
        int cid  = cids[i];
        int nxt  = (i == n_atoms - 1) ? n_clauses : cids[i + 1];
        bool last = (nxt != cid);
        int fz = (fid[i] << 8) | (last ? 0x80000000 : 0);   // byte offset, flag in bit31
        float g = last ? gate[cid] * leaf[cid] : 0.f;
        g_meta[i] = make_float4(A2, B2, __int_as_float(fz), g);
        // empty clauses in the gap (cid, nxt): their product is 1
        if (last) {
            for (int c = cid + 1; c < nxt; ++c)
                atomicAdd(&g_empty[c / cpc], gate[c] * leaf[c]);
        }
        if (i == 0) {
            for (int c = 0; c < cid; ++c)
                atomicAdd(&g_empty[c / cpc], gate[c] * leaf[c]);
        }
    }
    if (i <= NCHUNKS) {
        int target = i * cpc, lo = 0, hi = n_atoms;
        while (lo < hi) {
            int mid = (lo + hi) >> 1;
            if (cids[mid] < target) lo = mid + 1; else hi = mid;
        }
        g_chunk_start[i] = lo;
    }
}

__global__ __launch_bounds__(THREADS, 1)
void cln_main(const float* __restrict__ x, float* __restrict__ y, int nfeat) {
    extern __shared__ float xs[];            // feature-major: xs[feat*ROWS + row]
    __shared__ float ys[ROWS];

    const int rowBase = blockIdx.x * ROWS;

    // Stage transposed: warp shares f4, consecutive rows -> conflict-free STS.
    // GMEM side is 16B-granular (uncoalesced) but read-once; acceptable.
    const int n4 = nfeat >> 2;
    for (int i = threadIdx.x; i < n4 * ROWS; i += THREADS) {
        int f4 = i >> 6, row = i & (ROWS - 1);
        float4 v = reinterpret_cast<const float4*>(
                       x + (size_t)(rowBase + row) * nfeat)[f4];
        xs[(4 * f4 + 0) * ROWS + row] = v.x;
        xs[(4 * f4 + 1) * ROWS + row] = v.y;
        xs[(4 * f4 + 2) * ROWS + row] = v.z;
        xs[(4 * f4 + 3) * ROWS + row] = v.w;
    }
    if (threadIdx.x < ROWS) ys[threadIdx.x] = 0.f;
    __syncthreads();

    const int chunk = threadIdx.x >> 5;    // warp == chunk, 0..31
    const int lane  = threadIdx.x & 31;

    // lane owns adjacent rows 2*lane, 2*lane+1 -> single LDS.64 per atom
    const char* xbase = (const char*)xs + lane * 8;
    const float ec = g_empty[chunk];
    float y0 = ec, y1 = ec;
    float p0 = 1.f, p1 = 1.f;              // p >= 1 always

    const float4* __restrict__ mp = g_meta + g_chunk_start[chunk];
    const int n = g_chunk_start[chunk + 1] - g_chunk_start[chunk];

    // e clamped away from 0 so p==inf never meets e==0 (no NaN); p may reach
    // inf, then rcp gives 0 which matches reference underflow-to-zero.
#define LOADX(f)  (*(const float2*)(xbase + (f)))
#define EXPE(mm, xv) fmaxf(ex2a(fmaf((mm).x, (xv), (mm).y)), 1e-37f)

    int i = 0;
    for (; i + 4 <= n; i += 4) {
        float4 m0 = mp[i], m1 = mp[i + 1], m2 = mp[i + 2], m3 = mp[i + 3];
        int fz0 = __float_as_int(m0.z), fz1 = __float_as_int(m1.z);
        int fz2 = __float_as_int(m2.z), fz3 = __float_as_int(m3.z);
        float2 x0 = LOADX(fz0 & 0x7fffffff);
        float2 x1 = LOADX(fz1 & 0x7fffffff);
        float2 x2 = LOADX(fz2 & 0x7fffffff);
        float2 x3 = LOADX(fz3 & 0x7fffffff);

        // 8 independent exponentials (pipelined MUFU)
        float e00 = EXPE(m0, x0.x), e01 = EXPE(m1, x1.x);
        float e02 = EXPE(m2, x2.x), e03 = EXPE(m3, x3.x);
        float e10 = EXPE(m0, x0.y), e11 = EXPE(m1, x1.y);
        float e12 = EXPE(m2, x2.y), e13 = EXPE(m3, x3.y);

        // branchless p-chains with SEL resets; q's keep pre-reset values
        float q00 = fmaf(p0, e00, p0);  p0 = (fz0 < 0) ? 1.f : q00;
        float q01 = fmaf(p0, e01, p0);  p0 = (fz1 < 0) ? 1.f : q01;
        float q02 = fmaf(p0, e02, p0);  p0 = (fz2 < 0) ? 1.f : q02;
        float q03 = fmaf(p0, e03, p0);  p0 = (fz3 < 0) ? 1.f : q03;
        float q10 = fmaf(p1, e10, p1);  p1 = (fz0 < 0) ? 1.f : q10;
        float q11 = fmaf(p1, e11, p1);  p1 = (fz1 < 0) ? 1.f : q11;
        float q12 = fmaf(p1, e12, p1);  p1 = (fz2 < 0) ? 1.f : q12;
        float q13 = fmaf(p1, e13, p1);  p1 = (fz3 < 0) ? 1.f : q13;

        // rare path: flush finished clauses (one warp-uniform branch / 4 atoms)
        if ((fz0 | fz1 | fz2 | fz3) < 0) {
            if (fz0 < 0) { y0 = fmaf(m0.w, rcpa(q00), y0);
                           y1 = fmaf(m0.w, rcpa(q10), y1); }
            if (fz1 < 0) { y0 = fmaf(m1.w, rcpa(q01), y0);
                           y1 = fmaf(m1.w, rcpa(q11), y1); }
            if (fz2 < 0) { y0 = fmaf(m2.w, rcpa(q02), y0);
                           y1 = fmaf(m2.w, rcpa(q12), y1); }
            if (fz3 < 0) { y0 = fmaf(m3.w, rcpa(q03), y0);
                           y1 = fmaf(m3.w, rcpa(q13), y1); }
        }
    }
    for (; i < n; ++i) {
        float4 m = mp[i];
        int fz = __float_as_int(m.z);
        float2 xv = LOADX(fz & 0x7fffffff);
        float e0 = EXPE(m, xv.x), e1 = EXPE(m, xv.y);
        float q0 = fmaf(p0, e0, p0), q1 = fmaf(p1, e1, p1);
        if (fz < 0) {
            y0 = fmaf(m.w, rcpa(q0), y0);
            y1 = fmaf(m.w, rcpa(q1), y1);
            p0 = 1.f; p1 = 1.f;
        } else { p0 = q0; p1 = q1; }
    }
    // chunk is clause-aligned: last atom always flushes.

    atomicAdd(&ys[2 * lane],     y0);
    atomicAdd(&ys[2 * lane + 1], y1);
    __syncthreads();
    if (threadIdx.x < ROWS)
        y[rowBase + threadIdx.x] = ys[threadIdx.x];   // sole writer per row
}

extern "C" void kernel_launch(void* const* d_in, const int* in_sizes, int n_in,
                              void* d_out, int out_size) {
    const float* x    = (const float*)d_in[0];
    const float* w    = (const float*)d_in[1];
    const float* eta  = (const float*)d_in[2];
    const float* leaf = (const float*)d_in[3];
    const float* gate = (const float*)d_in[4];
    const int*   fid  = (const int*)d_in[5];
    const int*   csgn = (const int*)d_in[6];
    const int*   cids = (const int*)d_in[7];

    const int n_atoms   = in_sizes[1];
    const int n_clauses = in_sizes[3];
    const int batch     = out_size;
    const int nfeat     = in_sizes[0] / batch;
    const int cpc       = n_clauses / NCHUNKS;

    void* empty_ptr = nullptr;
    cudaGetSymbolAddress(&empty_ptr, g_empty);
    cudaMemsetAsync(empty_ptr, 0, NCHUNKS * sizeof(float));

    int setup_n = (n_atoms > n_clauses ? n_atoms : n_clauses);
    if (NCHUNKS + 1 > setup_n) setup_n = NCHUNKS + 1;
    cln_setup<<<(setup_n + 255) / 256, 256>>>(w, eta, leaf, gate, fid, csgn, cids,
                                              n_atoms, n_clauses, cpc);

    size_t smem = (size_t)nfeat * ROWS * sizeof(float);
    cudaFuncSetAttribute(cln_main, cudaFuncAttributeMaxDynamicSharedMemorySize,
                         (int)smem);
    cln_main<<<batch / ROWS, THREADS, smem>>>(x, (float*)d_out, nfeat);
}